// round 1
// baseline (speedup 1.0000x reference)
#include <cuda_runtime.h>
#include <math.h>

#define kN  100000   // nodes
#define kE0 160000   // edges per mask segment
#define kE  800000   // total edges
#define kD  128      // embed dim
#define kH  8        // heads
#define kDK 16       // head dim
#define kNG 50       // gaussians
#define kSCALE 0.25f // 1/sqrt(16)
#define kEPS 1e-5f

// ---------------- scratch (device globals; no runtime alloc) ----------------
__device__ float g_zk[kN * kD];        // 51.2 MB  key/query/value projection
__device__ float g_mask[kE * kH];      // 25.6 MB  attn_mask
__device__ float g_scores[kE * kH];    // 25.6 MB  exp(logits)
__device__ float g_denom[kN * kH];     //  3.2 MB  softmax denominators
__device__ float g_agg[kN * kD];       // 51.2 MB  attention aggregate
__device__ float g_x1[kN * kD];        // 51.2 MB  x + self_attn
__device__ float g_hbuf[kN * 2 * kD];  // 102.4 MB FF hidden

// ---------------- helpers ----------------
__device__ __forceinline__ float warp_sum(float v) {
    v += __shfl_xor_sync(0xffffffffu, v, 16);
    v += __shfl_xor_sync(0xffffffffu, v, 8);
    v += __shfl_xor_sync(0xffffffffu, v, 4);
    v += __shfl_xor_sync(0xffffffffu, v, 2);
    v += __shfl_xor_sync(0xffffffffu, v, 1);
    return v;
}

__device__ __forceinline__ float gelu_tanh(float v) {
    float c = v + 0.044715f * v * v * v;
    return 0.5f * v * (1.0f + tanhf(0.7978845608028654f * c));
}

// ---------------- K0: zero denom + agg ----------------
__global__ void k_init() {
    int idx = blockIdx.x * blockDim.x + threadIdx.x;
    int stride = gridDim.x * blockDim.x;
    for (int i = idx; i < kN * kH; i += stride) g_denom[i] = 0.0f;
    for (int i = idx; i < kN * kD; i += stride) g_agg[i] = 0.0f;
}

// ---------------- K1: zk = LN1(x) @ Wk + bk ----------------
// block = 128 threads (4 warps). tile = 16 rows. thread = 4 cols x 4 rows.
__global__ void k_ln_gemm(const float* __restrict__ x, const float* __restrict__ W,
                          const float* __restrict__ bias, const float* __restrict__ gam,
                          const float* __restrict__ bet) {
    __shared__ float zs[16][128];
    const int tid = threadIdx.x;
    const int w = tid >> 5, l = tid & 31;
    const int row0 = blockIdx.x << 4;

    const float4 gm = reinterpret_cast<const float4*>(gam)[l];
    const float4 bt = reinterpret_cast<const float4*>(bet)[l];
#pragma unroll
    for (int j = 0; j < 4; j++) {
        int r = (w << 2) + j;
        float4 xv = reinterpret_cast<const float4*>(x + (size_t)(row0 + r) * kD)[l];
        float s = xv.x + xv.y + xv.z + xv.w;
        float ss = xv.x * xv.x + xv.y * xv.y + xv.z * xv.z + xv.w * xv.w;
        s = warp_sum(s); ss = warp_sum(ss);
        float mu = s * (1.0f / 128.0f);
        float var = ss * (1.0f / 128.0f) - mu * mu;
        float rstd = rsqrtf(var + kEPS);
        float4 z;
        z.x = (xv.x - mu) * rstd * gm.x + bt.x;
        z.y = (xv.y - mu) * rstd * gm.y + bt.y;
        z.z = (xv.z - mu) * rstd * gm.z + bt.z;
        z.w = (xv.w - mu) * rstd * gm.w + bt.w;
        *reinterpret_cast<float4*>(&zs[r][l << 2]) = z;
    }
    __syncthreads();

    const float4* W4 = reinterpret_cast<const float4*>(W);
    float4 acc0, acc1, acc2, acc3;
    acc0 = acc1 = acc2 = acc3 = reinterpret_cast<const float4*>(bias)[l];
    const int rb = w << 2;
#pragma unroll 4
    for (int k = 0; k < 128; k++) {
        float4 wv = __ldg(&W4[k * 32 + l]);
        float z0 = zs[rb + 0][k], z1 = zs[rb + 1][k], z2 = zs[rb + 2][k], z3 = zs[rb + 3][k];
        acc0.x += z0 * wv.x; acc0.y += z0 * wv.y; acc0.z += z0 * wv.z; acc0.w += z0 * wv.w;
        acc1.x += z1 * wv.x; acc1.y += z1 * wv.y; acc1.z += z1 * wv.z; acc1.w += z1 * wv.w;
        acc2.x += z2 * wv.x; acc2.y += z2 * wv.y; acc2.z += z2 * wv.z; acc2.w += z2 * wv.w;
        acc3.x += z3 * wv.x; acc3.y += z3 * wv.y; acc3.z += z3 * wv.z; acc3.w += z3 * wv.w;
    }
    float4* o4 = reinterpret_cast<float4*>(g_zk + (size_t)(row0 + rb) * kD);
    o4[l] = acc0; o4[32 + l] = acc1; o4[64 + l] = acc2; o4[96 + l] = acc3;
}

// ---------------- K2: attention mask (gaussian smear + per-head linear) ----------------
// one thread per edge. blocks never straddle segments (E0 % 256 == 0).
__global__ void k_mask(const float* __restrict__ all_dist, const float* __restrict__ dist,
                       const float* __restrict__ cdd, const float* __restrict__ css,
                       const float* __restrict__ Wnn, const float* __restrict__ bnn,
                       const float* __restrict__ Wne, const float* __restrict__ bne,
                       const float* __restrict__ Wen, const float* __restrict__ ben,
                       const float* __restrict__ Wdd, const float* __restrict__ bdd,
                       const float* __restrict__ Wss, const float* __restrict__ bss) {
    __shared__ float Ws[kNG * kH];
    __shared__ float bs[kH];
    const int e0 = blockIdx.x << 8;
    const int seg = e0 / kE0;
    const float *Wp, *bp, *dp;
    float start, stop;
    if (seg == 0)      { Wp = Wnn; bp = bnn; dp = all_dist; start = 0.0f;  stop = 12.0f; }
    else if (seg == 1) { Wp = Wne; bp = bne; dp = dist;     start = 0.0f;  stop = 12.0f; }
    else if (seg == 2) { Wp = Wen; bp = ben; dp = dist;     start = 0.0f;  stop = 12.0f; }
    else if (seg == 3) { Wp = Wdd; bp = bdd; dp = cdd;      start = -1.0f; stop = 1.0f;  }
    else               { Wp = Wss; bp = bss; dp = css;      start = -1.0f; stop = 1.0f;  }
    for (int t = threadIdx.x; t < kNG * kH; t += 256) Ws[t] = Wp[t];
    if (threadIdx.x < kH) bs[threadIdx.x] = bp[threadIdx.x];
    __syncthreads();

    const int e = e0 + threadIdx.x;
    const float d = dp[e - seg * kE0];
    const float step = (stop - start) * (1.0f / 49.0f);
    const float coeff = -0.5f / (step * step);

    float a0 = bs[0], a1 = bs[1], a2 = bs[2], a3 = bs[3];
    float a4 = bs[4], a5 = bs[5], a6 = bs[6], a7 = bs[7];
#pragma unroll 5
    for (int g = 0; g < kNG; g++) {
        float t = d - (start + (float)g * step);
        float sm = expf(coeff * t * t);
        a0 += sm * Ws[g * 8 + 0]; a1 += sm * Ws[g * 8 + 1];
        a2 += sm * Ws[g * 8 + 2]; a3 += sm * Ws[g * 8 + 3];
        a4 += sm * Ws[g * 8 + 4]; a5 += sm * Ws[g * 8 + 5];
        a6 += sm * Ws[g * 8 + 6]; a7 += sm * Ws[g * 8 + 7];
    }
    float4* m4 = reinterpret_cast<float4*>(g_mask + (size_t)e * kH);
    m4[0] = make_float4(a0, a1, a2, a3);
    m4[1] = make_float4(a4, a5, a6, a7);
}

// ---------------- K3: scores = exp(scale*dot(q,kv) + mask); denom += scores ----------------
// 8 lanes per edge (one per head); each lane computes its full 16-dim head dot.
__global__ void k_scores(const int* __restrict__ edges) {
    const int gtid = blockIdx.x * blockDim.x + threadIdx.x;
    const int e = gtid >> 3;
    const int h = gtid & 7;
    const int i = edges[e];
    const int j = edges[kE + e];
    const float4* qa = reinterpret_cast<const float4*>(g_zk) + (size_t)i * 32 + h * 4;
    const float4* ka = reinterpret_cast<const float4*>(g_zk) + (size_t)j * 32 + h * 4;
    float acc = 0.0f;
#pragma unroll
    for (int t = 0; t < 4; t++) {
        float4 q = qa[t], k = ka[t];
        acc += q.x * k.x + q.y * k.y + q.z * k.z + q.w * k.w;
    }
    float sc = expf(kSCALE * acc + g_mask[(size_t)e * kH + h]);
    g_scores[(size_t)e * kH + h] = sc;
    atomicAdd(&g_denom[(size_t)i * kH + h], sc);
}

// ---------------- K4: agg[seg] += (scores/denom) * kv ----------------
// one warp per edge; lane l handles 4 contiguous floats; vector red to L2.
__global__ void k_scatter(const int* __restrict__ edges) {
    const int e = (blockIdx.x * blockDim.x + threadIdx.x) >> 5;
    const int l = threadIdx.x & 31;
    const int i = edges[e];
    const int j = edges[kE + e];
    float v = 0.0f;
    if (l < 8) v = g_scores[(size_t)e * kH + l] / g_denom[(size_t)i * kH + l];
    float s = __shfl_sync(0xffffffffu, v, l >> 2);
    float4 kv = reinterpret_cast<const float4*>(g_zk)[(size_t)j * 32 + l];
    float ox = s * kv.x, oy = s * kv.y, oz = s * kv.z, ow = s * kv.w;
    float* dst = g_agg + (size_t)i * kD + l * 4;
    asm volatile("red.global.add.v4.f32 [%0], {%1,%2,%3,%4};"
                 :: "l"(dst), "f"(ox), "f"(oy), "f"(oz), "f"(ow) : "memory");
}

// ---------------- K5: x1 = x + agg @ Wo + bo ----------------
__global__ void k_outproj(const float* __restrict__ x, const float* __restrict__ W,
                          const float* __restrict__ bias) {
    __shared__ float zs[16][128];
    const int tid = threadIdx.x;
    const int w = tid >> 5, l = tid & 31;
    const int row0 = blockIdx.x << 4;
#pragma unroll
    for (int j = 0; j < 4; j++) {
        int r = (w << 2) + j;
        float4 av = reinterpret_cast<const float4*>(g_agg + (size_t)(row0 + r) * kD)[l];
        *reinterpret_cast<float4*>(&zs[r][l << 2]) = av;
    }
    __syncthreads();

    const float4* W4 = reinterpret_cast<const float4*>(W);
    float4 acc0, acc1, acc2, acc3;
    acc0 = acc1 = acc2 = acc3 = reinterpret_cast<const float4*>(bias)[l];
    const int rb = w << 2;
#pragma unroll 4
    for (int k = 0; k < 128; k++) {
        float4 wv = __ldg(&W4[k * 32 + l]);
        float z0 = zs[rb + 0][k], z1 = zs[rb + 1][k], z2 = zs[rb + 2][k], z3 = zs[rb + 3][k];
        acc0.x += z0 * wv.x; acc0.y += z0 * wv.y; acc0.z += z0 * wv.z; acc0.w += z0 * wv.w;
        acc1.x += z1 * wv.x; acc1.y += z1 * wv.y; acc1.z += z1 * wv.z; acc1.w += z1 * wv.w;
        acc2.x += z2 * wv.x; acc2.y += z2 * wv.y; acc2.z += z2 * wv.z; acc2.w += z2 * wv.w;
        acc3.x += z3 * wv.x; acc3.y += z3 * wv.y; acc3.z += z3 * wv.z; acc3.w += z3 * wv.w;
    }
#pragma unroll
    for (int j = 0; j < 4; j++) {
        int r = row0 + rb + j;
        float4 xv = reinterpret_cast<const float4*>(x + (size_t)r * kD)[l];
        float4 a = (j == 0) ? acc0 : (j == 1) ? acc1 : (j == 2) ? acc2 : acc3;
        a.x += xv.x; a.y += xv.y; a.z += xv.z; a.w += xv.w;
        reinterpret_cast<float4*>(g_x1 + (size_t)r * kD)[l] = a;
    }
}

// ---------------- K6: h = gelu(LN2(x1) @ W1 + bf1) ---- grid.y selects 128-col half ----
__global__ void k_ff1(const float* __restrict__ W1, const float* __restrict__ bias,
                      const float* __restrict__ gam, const float* __restrict__ bet) {
    __shared__ float zs[16][128];
    const int tid = threadIdx.x;
    const int w = tid >> 5, l = tid & 31;
    const int row0 = blockIdx.x << 4;
    const int colb = blockIdx.y << 7;  // 0 or 128

    const float4 gm = reinterpret_cast<const float4*>(gam)[l];
    const float4 bt = reinterpret_cast<const float4*>(bet)[l];
#pragma unroll
    for (int j = 0; j < 4; j++) {
        int r = (w << 2) + j;
        float4 xv = reinterpret_cast<const float4*>(g_x1 + (size_t)(row0 + r) * kD)[l];
        float s = xv.x + xv.y + xv.z + xv.w;
        float ss = xv.x * xv.x + xv.y * xv.y + xv.z * xv.z + xv.w * xv.w;
        s = warp_sum(s); ss = warp_sum(ss);
        float mu = s * (1.0f / 128.0f);
        float var = ss * (1.0f / 128.0f) - mu * mu;
        float rstd = rsqrtf(var + kEPS);
        float4 z;
        z.x = (xv.x - mu) * rstd * gm.x + bt.x;
        z.y = (xv.y - mu) * rstd * gm.y + bt.y;
        z.z = (xv.z - mu) * rstd * gm.z + bt.z;
        z.w = (xv.w - mu) * rstd * gm.w + bt.w;
        *reinterpret_cast<float4*>(&zs[r][l << 2]) = z;
    }
    __syncthreads();

    const float4* W4 = reinterpret_cast<const float4*>(W1);
    float4 acc0, acc1, acc2, acc3;
    acc0 = acc1 = acc2 = acc3 = reinterpret_cast<const float4*>(bias)[(colb >> 2) + l];
    const int rb = w << 2;
#pragma unroll 4
    for (int k = 0; k < 128; k++) {
        float4 wv = __ldg(&W4[k * 64 + (colb >> 2) + l]);
        float z0 = zs[rb + 0][k], z1 = zs[rb + 1][k], z2 = zs[rb + 2][k], z3 = zs[rb + 3][k];
        acc0.x += z0 * wv.x; acc0.y += z0 * wv.y; acc0.z += z0 * wv.z; acc0.w += z0 * wv.w;
        acc1.x += z1 * wv.x; acc1.y += z1 * wv.y; acc1.z += z1 * wv.z; acc1.w += z1 * wv.w;
        acc2.x += z2 * wv.x; acc2.y += z2 * wv.y; acc2.z += z2 * wv.z; acc2.w += z2 * wv.w;
        acc3.x += z3 * wv.x; acc3.y += z3 * wv.y; acc3.z += z3 * wv.z; acc3.w += z3 * wv.w;
    }
#pragma unroll
    for (int j = 0; j < 4; j++) {
        float4 a = (j == 0) ? acc0 : (j == 1) ? acc1 : (j == 2) ? acc2 : acc3;
        a.x = gelu_tanh(a.x); a.y = gelu_tanh(a.y); a.z = gelu_tanh(a.z); a.w = gelu_tanh(a.w);
        float* hp = g_hbuf + (size_t)(row0 + rb + j) * 256 + colb;
        reinterpret_cast<float4*>(hp)[l] = a;
    }
}

// ---------------- K7: out = x1 + h @ W2 + bf2 ----------------
__global__ void k_ff2(const float* __restrict__ W2, const float* __restrict__ bias,
                      float* __restrict__ out) {
    __shared__ float hs[16][256];
    const int tid = threadIdx.x;
    const int w = tid >> 5, l = tid & 31;
    const int row0 = blockIdx.x << 4;
#pragma unroll
    for (int j = 0; j < 4; j++) {
        int r = (w << 2) + j;
        const float4* hp = reinterpret_cast<const float4*>(g_hbuf + (size_t)(row0 + r) * 256);
        *reinterpret_cast<float4*>(&hs[r][l << 2]) = hp[l];
        *reinterpret_cast<float4*>(&hs[r][128 + (l << 2)]) = hp[32 + l];
    }
    __syncthreads();

    const float4* W4 = reinterpret_cast<const float4*>(W2);
    float4 acc0, acc1, acc2, acc3;
    acc0 = acc1 = acc2 = acc3 = reinterpret_cast<const float4*>(bias)[l];
    const int rb = w << 2;
#pragma unroll 4
    for (int k = 0; k < 256; k++) {
        float4 wv = __ldg(&W4[k * 32 + l]);
        float z0 = hs[rb + 0][k], z1 = hs[rb + 1][k], z2 = hs[rb + 2][k], z3 = hs[rb + 3][k];
        acc0.x += z0 * wv.x; acc0.y += z0 * wv.y; acc0.z += z0 * wv.z; acc0.w += z0 * wv.w;
        acc1.x += z1 * wv.x; acc1.y += z1 * wv.y; acc1.z += z1 * wv.z; acc1.w += z1 * wv.w;
        acc2.x += z2 * wv.x; acc2.y += z2 * wv.y; acc2.z += z2 * wv.z; acc2.w += z2 * wv.w;
        acc3.x += z3 * wv.x; acc3.y += z3 * wv.y; acc3.z += z3 * wv.z; acc3.w += z3 * wv.w;
    }
#pragma unroll
    for (int j = 0; j < 4; j++) {
        int r = row0 + rb + j;
        float4 xv = reinterpret_cast<const float4*>(g_x1 + (size_t)r * kD)[l];
        float4 a = (j == 0) ? acc0 : (j == 1) ? acc1 : (j == 2) ? acc2 : acc3;
        a.x += xv.x; a.y += xv.y; a.z += xv.z; a.w += xv.w;
        reinterpret_cast<float4*>(out + (size_t)r * kD)[l] = a;
    }
}

// ---------------- launch ----------------
extern "C" void kernel_launch(void* const* d_in, const int* in_sizes, int n_in,
                              void* d_out, int out_size) {
    const float* x        = (const float*)d_in[0];
    const int*   edges    = (const int*)  d_in[1];
    const float* all_dist = (const float*)d_in[2];
    const float* dist     = (const float*)d_in[3];
    const float* cdd      = (const float*)d_in[4];
    const float* css      = (const float*)d_in[5];
    const float* Wk       = (const float*)d_in[6];
    const float* bk       = (const float*)d_in[7];
    const float* Wnn      = (const float*)d_in[8];
    const float* bnn      = (const float*)d_in[9];
    const float* Wne      = (const float*)d_in[10];
    const float* bne      = (const float*)d_in[11];
    const float* Wen      = (const float*)d_in[12];
    const float* ben      = (const float*)d_in[13];
    const float* Wdd      = (const float*)d_in[14];
    const float* bdd      = (const float*)d_in[15];
    const float* Wss      = (const float*)d_in[16];
    const float* bss      = (const float*)d_in[17];
    const float* Wo       = (const float*)d_in[18];
    const float* bo       = (const float*)d_in[19];
    const float* ln1_g    = (const float*)d_in[20];
    const float* ln1_b    = (const float*)d_in[21];
    const float* ln2_g    = (const float*)d_in[22];
    const float* ln2_b    = (const float*)d_in[23];
    const float* W1       = (const float*)d_in[24];
    const float* bf1      = (const float*)d_in[25];
    const float* W2       = (const float*)d_in[26];
    const float* bf2      = (const float*)d_in[27];
    float* out = (float*)d_out;

    k_init<<<1024, 256>>>();
    k_ln_gemm<<<kN / 16, 128>>>(x, Wk, bk, ln1_g, ln1_b);
    k_mask<<<kE / 256, 256>>>(all_dist, dist, cdd, css,
                              Wnn, bnn, Wne, bne, Wen, ben, Wdd, bdd, Wss, bss);
    k_scores<<<kE * kH / 256, 256>>>(edges);
    k_scatter<<<kE / 8, 256>>>(edges);
    k_outproj<<<kN / 16, 128>>>(x, Wo, bo);
    dim3 g6(kN / 16, 2);
    k_ff1<<<g6, 128>>>(W1, bf1, ln2_g, ln2_b);
    k_ff2<<<kN / 16, 128>>>(W2, bf2, out);
}